// round 3
// baseline (speedup 1.0000x reference)
#include <cuda_runtime.h>
#include <math.h>

// FeatureSimilarityAttention — GB300 sm_103a
// B=8, L=512, D=512, N_FEAT=11. Outputs: out [B,L,D] then attn [B,L,L] (fp32).
//
// Pipeline:
//   1) 5x projection GEMMs (NT): qp,kp,vp,qf,kf
//   2) extract xf (first 11 feats, padded to 16) ; feat_attn masked softmax
//   3) qf2 = feat_attn @ qf ; kf2 = feat_attn @ kf   (batched NN)
//   4) attn = tanh( (qp.kp^T + qf2.kf2^T)/sqrt(D) ) masked on keys (batched dual-NT)
//   5) o1 = attn @ vp (batched NN)
//   6) pre = o1 @ Wfc^T + q  (NT + residual)
//   7) LayerNorm(pre) -> out

#define BB   8
#define LL   512
#define DD   512
#define TOT  (BB * LL * DD)        // 2097152
#define BSTR ((size_t)(LL * DD))   // per-batch stride 262144

// ---------------- scratch (no allocations allowed) ----------------
__device__ __align__(16) float g_qp[TOT];
__device__ __align__(16) float g_kp[TOT];
__device__ __align__(16) float g_vp[TOT];
__device__ __align__(16) float g_qf[TOT];
__device__ __align__(16) float g_kf[TOT];
__device__ __align__(16) float g_qf2[TOT];
__device__ __align__(16) float g_kf2[TOT];
__device__ __align__(16) float g_feat[TOT];
__device__ __align__(16) float g_o1[TOT];
__device__ __align__(16) float g_pre[TOT];
__device__ __align__(16) float g_attn[TOT];
__device__ __align__(16) float g_xfc[BB * LL * 16];

// ---------------- tiled fp32 GEMM ----------------
// 64x64 tile, BK=16, 256 threads, 4x4 per-thread microtile.
// BNT=true : B stored [N,K] row-major (C = A * B^T)
// BNT=false: B stored [K,N] row-major (C = A * B)
// DUAL: accumulate a second (A2,B2) pair over the same K (for the dual score GEMM)
// EPI: 0 = plain store, 1 = masked tanh(v*scale), 2 = add residual
#define GBM 64
#define GBN 64
#define GBK 16
#define GTM 4
#define GTN 4
#define GPAD 4

template<bool BNT, bool DUAL, int EPI>
__global__ __launch_bounds__(256)
void gemm_kernel(const float* __restrict__ A, const float* __restrict__ Bm,
                 const float* __restrict__ A2, const float* __restrict__ B2,
                 float* __restrict__ C, int K, int N,
                 size_t sA, size_t sB, size_t sC,
                 const float* __restrict__ resid,
                 const int* __restrict__ lens, float scale)
{
    __shared__ float As[GBK][GBM + GPAD];
    __shared__ float Bs[GBK][GBN + GPAD];

    const int z   = blockIdx.z;
    const int tid = threadIdx.x;
    const int tr  = tid >> 4;        // 0..15
    const int tc  = tid & 15;        // 0..15
    const int m0  = blockIdx.y * GBM;
    const int n0  = blockIdx.x * GBN;

    float acc[GTM][GTN];
#pragma unroll
    for (int i = 0; i < GTM; i++)
#pragma unroll
        for (int j = 0; j < GTN; j++) acc[i][j] = 0.0f;

    const int npair = DUAL ? 2 : 1;
    for (int p = 0; p < npair; p++) {
        const float* Ap = (p == 0 ? A  : A2) + (size_t)z * sA;
        const float* Bp = (p == 0 ? Bm : B2) + (size_t)z * sB;

        for (int k0 = 0; k0 < K; k0 += GBK) {
            // A tile: 64 rows x 16 k, one float4 per thread, transposed into As
            {
                const int r = tid >> 2;            // 0..63
                const int c = (tid & 3) << 2;      // 0,4,8,12
                const float4 a4 = *(const float4*)(Ap + (size_t)(m0 + r) * K + k0 + c);
                As[c + 0][r] = a4.x; As[c + 1][r] = a4.y;
                As[c + 2][r] = a4.z; As[c + 3][r] = a4.w;
            }
            if (BNT) {
                const int r = tid >> 2;            // n 0..63
                const int c = (tid & 3) << 2;      // k 0,4,8,12
                const float4 b4 = *(const float4*)(Bp + (size_t)(n0 + r) * K + k0 + c);
                Bs[c + 0][r] = b4.x; Bs[c + 1][r] = b4.y;
                Bs[c + 2][r] = b4.z; Bs[c + 3][r] = b4.w;
            } else {
                const int r = tid >> 4;            // k 0..15
                const int c = (tid & 15) << 2;     // n 0..60
                const float4 b4 = *(const float4*)(Bp + (size_t)(k0 + r) * N + n0 + c);
                *(float4*)(&Bs[r][c]) = b4;
            }
            __syncthreads();

#pragma unroll
            for (int kk = 0; kk < GBK; kk++) {
                float ra[GTM], rb[GTN];
                *(float4*)ra = *(const float4*)(&As[kk][tr * GTM]);
                *(float4*)rb = *(const float4*)(&Bs[kk][tc * GTN]);
#pragma unroll
                for (int i = 0; i < GTM; i++)
#pragma unroll
                    for (int j = 0; j < GTN; j++)
                        acc[i][j] = fmaf(ra[i], rb[j], acc[i][j]);
            }
            __syncthreads();
        }
    }

    const int len = (EPI == 1) ? lens[z] : 0;
    float* Cb = C + (size_t)z * sC;
#pragma unroll
    for (int i = 0; i < GTM; i++) {
        const int row  = m0 + tr * GTM + i;
        const int col0 = n0 + tc * GTN;
        float vv[4];
#pragma unroll
        for (int j = 0; j < GTN; j++) {
            float val = acc[i][j];
            if (EPI == 1) val = (col0 + j < len) ? tanhf(val * scale) : 0.0f;
            vv[j] = val;
        }
        if (EPI == 2) {
            const float4 r4 = *(const float4*)(resid + (size_t)row * N + col0);
            vv[0] += r4.x; vv[1] += r4.y; vv[2] += r4.z; vv[3] += r4.w;
        }
        float4 v4; v4.x = vv[0]; v4.y = vv[1]; v4.z = vv[2]; v4.w = vv[3];
        *(float4*)(Cb + (size_t)row * N + col0) = v4;
    }
}

// ---------------- extract xf = x[:,:,:11] into padded [B,L,16] ----------------
__global__ void extract_kernel(const float* __restrict__ x, float* __restrict__ xfc)
{
    const int idx = blockIdx.x * 256 + threadIdx.x;
    if (idx >= BB * LL * 16) return;
    const int f  = idx & 15;
    const int bl = idx >> 4;
    xfc[idx] = (f < 11) ? x[(size_t)bl * DD + f] : 0.0f;
}

// ---------------- feat_attn: masked softmax over pairwise |dx|.imp ----------------
// grid (L, B), 256 threads; one block computes one query row i.
__global__ __launch_bounds__(256)
void feat_kernel(const float* __restrict__ xfc, const float* __restrict__ imp,
                 const int* __restrict__ lens, float* __restrict__ feat)
{
    const int b = blockIdx.y, i = blockIdx.x, tid = threadIdx.x;
    __shared__ float sx[LL * 11];
    __shared__ float sv[LL];
    __shared__ float red[256];

    const float* xb = xfc + (size_t)b * (LL * 16);
    for (int idx = tid; idx < LL * 11; idx += 256) {
        const int j = idx / 11;
        const int f = idx - j * 11;
        sx[idx] = xb[j * 16 + f];
    }
    __syncthreads();

    float xi[11], fi[11];
#pragma unroll
    for (int f = 0; f < 11; f++) { xi[f] = sx[i * 11 + f]; fi[f] = imp[f]; }

    const int len = lens[b];
    float lmax = -3.0e38f;
    for (int j = tid; j < LL; j += 256) {
        float s = -1.0e9f;
        if (j < len) {
            s = 0.0f;
#pragma unroll
            for (int f = 0; f < 11; f++)
                s = fmaf(fabsf(xi[f] - sx[j * 11 + f]), fi[f], s);
        }
        sv[j] = s;
        lmax = fmaxf(lmax, s);
    }
    red[tid] = lmax;
    __syncthreads();
    for (int off = 128; off > 0; off >>= 1) {
        if (tid < off) red[tid] = fmaxf(red[tid], red[tid + off]);
        __syncthreads();
    }
    const float mx = red[0];
    __syncthreads();

    float lsum = 0.0f;
    for (int j = tid; j < LL; j += 256) {
        const float e = (j < len) ? expf(sv[j] - mx) : 0.0f;
        sv[j] = e;
        lsum += e;
    }
    red[tid] = lsum;
    __syncthreads();
    for (int off = 128; off > 0; off >>= 1) {
        if (tid < off) red[tid] += red[tid + off];
        __syncthreads();
    }
    const float inv = 1.0f / red[0];

    float* fr = feat + ((size_t)b * LL + i) * LL;
    for (int j = tid; j < LL; j += 256) fr[j] = sv[j] * inv;
}

// ---------------- LayerNorm over last dim (512), block per row ----------------
__global__ __launch_bounds__(256)
void ln_kernel(const float* __restrict__ pre, const float* __restrict__ gamma,
               const float* __restrict__ beta, float* __restrict__ out)
{
    const int row = blockIdx.x, tid = threadIdx.x;
    const float* p = pre + (size_t)row * DD;
    const float v0 = p[tid];
    const float v1 = p[tid + 256];

    __shared__ float r1[256], r2[256];
    r1[tid] = v0 + v1;
    r2[tid] = v0 * v0 + v1 * v1;
    __syncthreads();
    for (int off = 128; off > 0; off >>= 1) {
        if (tid < off) { r1[tid] += r1[tid + off]; r2[tid] += r2[tid + off]; }
        __syncthreads();
    }
    const float mu  = r1[0] * (1.0f / 512.0f);
    const float var = r2[0] * (1.0f / 512.0f) - mu * mu;
    const float inv = rsqrtf(var + 1e-6f);

    out[(size_t)row * DD + tid]       = (v0 - mu) * inv * gamma[tid]       + beta[tid];
    out[(size_t)row * DD + tid + 256] = (v1 - mu) * inv * gamma[tid + 256] + beta[tid + 256];
}

// ---------------- launch ----------------
extern "C" void kernel_launch(void* const* d_in, const int* in_sizes, int n_in,
                              void* d_out, int out_size)
{
    const float* q    = (const float*)d_in[0];
    const float* k    = (const float*)d_in[1];
    const float* v    = (const float*)d_in[2];
    const float* x    = (const float*)d_in[3];
    const int*   lens = (const int*)  d_in[4];
    const float* Wq   = (const float*)d_in[5];
    const float* Wk   = (const float*)d_in[6];
    const float* Wv   = (const float*)d_in[7];
    const float* Wqf  = (const float*)d_in[8];
    const float* Wkf  = (const float*)d_in[9];
    const float* Wfc  = (const float*)d_in[10];
    const float* imp  = (const float*)d_in[11];
    const float* gmm  = (const float*)d_in[12];
    const float* bta  = (const float*)d_in[13];
    float* out = (float*)d_out;

    float *qp, *kp, *vp, *qf, *kf, *qf2, *kf2, *feat, *o1, *pre, *attnS, *xfc;
    cudaGetSymbolAddress((void**)&qp,   g_qp);
    cudaGetSymbolAddress((void**)&kp,   g_kp);
    cudaGetSymbolAddress((void**)&vp,   g_vp);
    cudaGetSymbolAddress((void**)&qf,   g_qf);
    cudaGetSymbolAddress((void**)&kf,   g_kf);
    cudaGetSymbolAddress((void**)&qf2,  g_qf2);
    cudaGetSymbolAddress((void**)&kf2,  g_kf2);
    cudaGetSymbolAddress((void**)&feat, g_feat);
    cudaGetSymbolAddress((void**)&o1,   g_o1);
    cudaGetSymbolAddress((void**)&pre,  g_pre);
    cudaGetSymbolAddress((void**)&attnS,g_attn);
    cudaGetSymbolAddress((void**)&xfc,  g_xfc);

    // attn is the second tuple output; write it directly into d_out if there is room.
    float* attn_ptr = (out_size >= 2 * TOT) ? (out + TOT) : attnS;

    const float scale = 1.0f / sqrtf((float)DD);   // 1/sqrt(512)
    const dim3 blk(256);
    const dim3 gproj(DD / GBN, (BB * LL) / GBM, 1);  // (8, 64)
    const dim3 gbat (LL / GBN, LL / GBM, BB);        // (8, 8, 8)

    // 1) projections (M = B*L = 4096 flattened, NT vs row-major [E,D] weights)
    gemm_kernel<true , false, 0><<<gproj, blk>>>(q, Wq , nullptr, nullptr, qp, DD, DD, 0, 0, 0, nullptr, nullptr, 0.f);
    gemm_kernel<true , false, 0><<<gproj, blk>>>(k, Wk , nullptr, nullptr, kp, DD, DD, 0, 0, 0, nullptr, nullptr, 0.f);
    gemm_kernel<true , false, 0><<<gproj, blk>>>(v, Wv , nullptr, nullptr, vp, DD, DD, 0, 0, 0, nullptr, nullptr, 0.f);
    gemm_kernel<true , false, 0><<<gproj, blk>>>(q, Wqf, nullptr, nullptr, qf, DD, DD, 0, 0, 0, nullptr, nullptr, 0.f);
    gemm_kernel<true , false, 0><<<gproj, blk>>>(k, Wkf, nullptr, nullptr, kf, DD, DD, 0, 0, 0, nullptr, nullptr, 0.f);

    // 2) feature-similarity attention weights
    extract_kernel<<<(BB * LL * 16 + 255) / 256, 256>>>(x, xfc);
    feat_kernel<<<dim3(LL, BB), blk>>>(xfc, imp, lens, feat);

    // 3) qf2 / kf2 (batched NN)
    gemm_kernel<false, false, 0><<<gbat, blk>>>(feat, qf, nullptr, nullptr, qf2, LL, DD, BSTR, BSTR, BSTR, nullptr, nullptr, 0.f);
    gemm_kernel<false, false, 0><<<gbat, blk>>>(feat, kf, nullptr, nullptr, kf2, LL, DD, BSTR, BSTR, BSTR, nullptr, nullptr, 0.f);

    // 4) attn = tanh((qp.kp^T + qf2.kf2^T)/temp), key-masked (batched dual-NT)
    gemm_kernel<true , true , 1><<<gbat, blk>>>(qp, kp, qf2, kf2, attn_ptr, DD, LL, BSTR, BSTR, BSTR, nullptr, lens, scale);

    // 5) o1 = attn @ vp (batched NN)
    gemm_kernel<false, false, 0><<<gbat, blk>>>(attn_ptr, vp, nullptr, nullptr, o1, LL, DD, BSTR, BSTR, BSTR, nullptr, nullptr, 0.f);

    // 6) pre = o1 @ Wfc^T + q (NT + residual)
    gemm_kernel<true , false, 2><<<gproj, blk>>>(o1, Wfc, nullptr, nullptr, pre, DD, DD, 0, 0, 0, q, nullptr, 0.f);

    // 7) LayerNorm -> out
    ln_kernel<<<BB * LL, blk>>>(pre, gmm, bta, out);
}

// round 5
// speedup vs baseline: 1.0030x; 1.0030x over previous
#include <cuda_runtime.h>
#include <math.h>

// FeatureSimilarityAttention — GB300 sm_103a
// B=8, L=512, D=512, N_FEAT=11. Outputs: out [B,L,D] then attn [B,L,L] (fp32).
//
// Pipeline:
//   1) 5x projection GEMMs (NT): qp,kp,vp,qf,kf
//   2) extract xf (first 11 feats, padded to 16) ; feat_attn masked softmax
//   3) qf2 = feat_attn @ qf ; kf2 = feat_attn @ kf   (batched NN)
//   4) attn = tanh( (qp.kp^T + qf2.kf2^T)/sqrt(D) ) masked on keys (batched dual-NT)
//   5) o1 = attn @ vp (batched NN)
//   6) pre = o1 @ Wfc^T + q  (NT + residual)
//   7) LayerNorm(pre) -> out

#define BB   8
#define LL   512
#define DD   512
#define TOT  (BB * LL * DD)        // 2097152
#define BSTR ((size_t)(LL * DD))   // per-batch stride 262144

// ---------------- scratch (no allocations allowed) ----------------
__device__ __align__(16) float g_qp[TOT];
__device__ __align__(16) float g_kp[TOT];
__device__ __align__(16) float g_vp[TOT];
__device__ __align__(16) float g_qf[TOT];
__device__ __align__(16) float g_kf[TOT];
__device__ __align__(16) float g_qf2[TOT];
__device__ __align__(16) float g_kf2[TOT];
__device__ __align__(16) float g_feat[TOT];
__device__ __align__(16) float g_o1[TOT];
__device__ __align__(16) float g_pre[TOT];
__device__ __align__(16) float g_attn[TOT];
__device__ __align__(16) float g_xfc[BB * LL * 16];

// ---------------- tiled fp32 GEMM ----------------
// 64x64 tile, BK=16, 256 threads, 4x4 per-thread microtile.
// BNT=true : B stored [N,K] row-major (C = A * B^T)
// BNT=false: B stored [K,N] row-major (C = A * B)
// DUAL: accumulate a second (A2,B2) pair over the same K (for the dual score GEMM)
// EPI: 0 = plain store, 1 = masked tanh(v*scale), 2 = add residual
#define GBM 64
#define GBN 64
#define GBK 16
#define GTM 4
#define GTN 4
#define GPAD 4

template<bool BNT, bool DUAL, int EPI>
__global__ __launch_bounds__(256)
void gemm_kernel(const float* __restrict__ A, const float* __restrict__ Bm,
                 const float* __restrict__ A2, const float* __restrict__ B2,
                 float* __restrict__ C, int K, int N,
                 size_t sA, size_t sB, size_t sC,
                 const float* __restrict__ resid,
                 const int* __restrict__ lens, float scale)
{
    __shared__ float As[GBK][GBM + GPAD];
    __shared__ float Bs[GBK][GBN + GPAD];

    const int z   = blockIdx.z;
    const int tid = threadIdx.x;
    const int tr  = tid >> 4;        // 0..15
    const int tc  = tid & 15;        // 0..15
    const int m0  = blockIdx.y * GBM;
    const int n0  = blockIdx.x * GBN;

    float acc[GTM][GTN];
#pragma unroll
    for (int i = 0; i < GTM; i++)
#pragma unroll
        for (int j = 0; j < GTN; j++) acc[i][j] = 0.0f;

    const int npair = DUAL ? 2 : 1;
    for (int p = 0; p < npair; p++) {
        const float* Ap = (p == 0 ? A  : A2) + (size_t)z * sA;
        const float* Bp = (p == 0 ? Bm : B2) + (size_t)z * sB;

        for (int k0 = 0; k0 < K; k0 += GBK) {
            // A tile: 64 rows x 16 k, one float4 per thread, transposed into As
            {
                const int r = tid >> 2;            // 0..63
                const int c = (tid & 3) << 2;      // 0,4,8,12
                const float4 a4 = *(const float4*)(Ap + (size_t)(m0 + r) * K + k0 + c);
                As[c + 0][r] = a4.x; As[c + 1][r] = a4.y;
                As[c + 2][r] = a4.z; As[c + 3][r] = a4.w;
            }
            if (BNT) {
                const int r = tid >> 2;            // n 0..63
                const int c = (tid & 3) << 2;      // k 0,4,8,12
                const float4 b4 = *(const float4*)(Bp + (size_t)(n0 + r) * K + k0 + c);
                Bs[c + 0][r] = b4.x; Bs[c + 1][r] = b4.y;
                Bs[c + 2][r] = b4.z; Bs[c + 3][r] = b4.w;
            } else {
                const int r = tid >> 4;            // k 0..15
                const int c = (tid & 15) << 2;     // n 0..60
                const float4 b4 = *(const float4*)(Bp + (size_t)(k0 + r) * N + n0 + c);
                *(float4*)(&Bs[r][c]) = b4;
            }
            __syncthreads();

#pragma unroll
            for (int kk = 0; kk < GBK; kk++) {
                float ra[GTM], rb[GTN];
                *(float4*)ra = *(const float4*)(&As[kk][tr * GTM]);
                *(float4*)rb = *(const float4*)(&Bs[kk][tc * GTN]);
#pragma unroll
                for (int i = 0; i < GTM; i++)
#pragma unroll
                    for (int j = 0; j < GTN; j++)
                        acc[i][j] = fmaf(ra[i], rb[j], acc[i][j]);
            }
            __syncthreads();
        }
    }

    const int len = (EPI == 1) ? lens[z] : 0;
    float* Cb = C + (size_t)z * sC;
#pragma unroll
    for (int i = 0; i < GTM; i++) {
        const int row  = m0 + tr * GTM + i;
        const int col0 = n0 + tc * GTN;
        float vv[4];
#pragma unroll
        for (int j = 0; j < GTN; j++) {
            float val = acc[i][j];
            if (EPI == 1) val = (col0 + j < len) ? tanhf(val * scale) : 0.0f;
            vv[j] = val;
        }
        if (EPI == 2) {
            const float4 r4 = *(const float4*)(resid + (size_t)row * N + col0);
            vv[0] += r4.x; vv[1] += r4.y; vv[2] += r4.z; vv[3] += r4.w;
        }
        float4 v4; v4.x = vv[0]; v4.y = vv[1]; v4.z = vv[2]; v4.w = vv[3];
        *(float4*)(Cb + (size_t)row * N + col0) = v4;
    }
}

// ---------------- extract xf = x[:,:,:11] into padded [B,L,16] ----------------
__global__ void extract_kernel(const float* __restrict__ x, float* __restrict__ xfc)
{
    const int idx = blockIdx.x * 256 + threadIdx.x;
    if (idx >= BB * LL * 16) return;
    const int f  = idx & 15;
    const int bl = idx >> 4;
    xfc[idx] = (f < 11) ? x[(size_t)bl * DD + f] : 0.0f;
}

// ---------------- feat_attn: masked softmax over pairwise |dx|.imp ----------------
// grid (L, B), 256 threads; one block computes one query row i.
__global__ __launch_bounds__(256)
void feat_kernel(const float* __restrict__ xfc, const float* __restrict__ imp,
                 const int* __restrict__ lens, float* __restrict__ feat)
{
    const int b = blockIdx.y, i = blockIdx.x, tid = threadIdx.x;
    __shared__ float sx[LL * 11];
    __shared__ float sv[LL];
    __shared__ float red[256];

    const float* xb = xfc + (size_t)b * (LL * 16);
    for (int idx = tid; idx < LL * 11; idx += 256) {
        const int j = idx / 11;
        const int f = idx - j * 11;
        sx[idx] = xb[j * 16 + f];
    }
    __syncthreads();

    float xi[11], fi[11];
#pragma unroll
    for (int f = 0; f < 11; f++) { xi[f] = sx[i * 11 + f]; fi[f] = imp[f]; }

    const int len = lens[b];
    float lmax = -3.0e38f;
    for (int j = tid; j < LL; j += 256) {
        float s = -1.0e9f;
        if (j < len) {
            s = 0.0f;
#pragma unroll
            for (int f = 0; f < 11; f++)
                s = fmaf(fabsf(xi[f] - sx[j * 11 + f]), fi[f], s);
        }
        sv[j] = s;
        lmax = fmaxf(lmax, s);
    }
    red[tid] = lmax;
    __syncthreads();
    for (int off = 128; off > 0; off >>= 1) {
        if (tid < off) red[tid] = fmaxf(red[tid], red[tid + off]);
        __syncthreads();
    }
    const float mx = red[0];
    __syncthreads();

    float lsum = 0.0f;
    for (int j = tid; j < LL; j += 256) {
        const float e = (j < len) ? expf(sv[j] - mx) : 0.0f;
        sv[j] = e;
        lsum += e;
    }
    red[tid] = lsum;
    __syncthreads();
    for (int off = 128; off > 0; off >>= 1) {
        if (tid < off) red[tid] += red[tid + off];
        __syncthreads();
    }
    const float inv = 1.0f / red[0];

    float* fr = feat + ((size_t)b * LL + i) * LL;
    for (int j = tid; j < LL; j += 256) fr[j] = sv[j] * inv;
}

// ---------------- LayerNorm over last dim (512), block per row ----------------
__global__ __launch_bounds__(256)
void ln_kernel(const float* __restrict__ pre, const float* __restrict__ gamma,
               const float* __restrict__ beta, float* __restrict__ out)
{
    const int row = blockIdx.x, tid = threadIdx.x;
    const float* p = pre + (size_t)row * DD;
    const float v0 = p[tid];
    const float v1 = p[tid + 256];

    __shared__ float r1[256], r2[256];
    r1[tid] = v0 + v1;
    r2[tid] = v0 * v0 + v1 * v1;
    __syncthreads();
    for (int off = 128; off > 0; off >>= 1) {
        if (tid < off) { r1[tid] += r1[tid + off]; r2[tid] += r2[tid + off]; }
        __syncthreads();
    }
    const float mu  = r1[0] * (1.0f / 512.0f);
    const float var = r2[0] * (1.0f / 512.0f) - mu * mu;
    const float inv = rsqrtf(var + 1e-6f);

    out[(size_t)row * DD + tid]       = (v0 - mu) * inv * gamma[tid]       + beta[tid];
    out[(size_t)row * DD + tid + 256] = (v1 - mu) * inv * gamma[tid + 256] + beta[tid + 256];
}

// ---------------- launch ----------------
extern "C" void kernel_launch(void* const* d_in, const int* in_sizes, int n_in,
                              void* d_out, int out_size)
{
    const float* q    = (const float*)d_in[0];
    const float* k    = (const float*)d_in[1];
    const float* v    = (const float*)d_in[2];
    const float* x    = (const float*)d_in[3];
    const int*   lens = (const int*)  d_in[4];
    const float* Wq   = (const float*)d_in[5];
    const float* Wk   = (const float*)d_in[6];
    const float* Wv   = (const float*)d_in[7];
    const float* Wqf  = (const float*)d_in[8];
    const float* Wkf  = (const float*)d_in[9];
    const float* Wfc  = (const float*)d_in[10];
    const float* imp  = (const float*)d_in[11];
    const float* gmm  = (const float*)d_in[12];
    const float* bta  = (const float*)d_in[13];
    float* out = (float*)d_out;

    float *qp, *kp, *vp, *qf, *kf, *qf2, *kf2, *feat, *o1, *pre, *attnS, *xfc;
    cudaGetSymbolAddress((void**)&qp,   g_qp);
    cudaGetSymbolAddress((void**)&kp,   g_kp);
    cudaGetSymbolAddress((void**)&vp,   g_vp);
    cudaGetSymbolAddress((void**)&qf,   g_qf);
    cudaGetSymbolAddress((void**)&kf,   g_kf);
    cudaGetSymbolAddress((void**)&qf2,  g_qf2);
    cudaGetSymbolAddress((void**)&kf2,  g_kf2);
    cudaGetSymbolAddress((void**)&feat, g_feat);
    cudaGetSymbolAddress((void**)&o1,   g_o1);
    cudaGetSymbolAddress((void**)&pre,  g_pre);
    cudaGetSymbolAddress((void**)&attnS,g_attn);
    cudaGetSymbolAddress((void**)&xfc,  g_xfc);

    // attn is the second tuple output; write it directly into d_out if there is room.
    float* attn_ptr = (out_size >= 2 * TOT) ? (out + TOT) : attnS;

    const float scale = 1.0f / sqrtf((float)DD);   // 1/sqrt(512)
    const dim3 blk(256);
    const dim3 gproj(DD / GBN, (BB * LL) / GBM, 1);  // (8, 64)
    const dim3 gbat (LL / GBN, LL / GBM, BB);        // (8, 8, 8)

    // 1) projections (M = B*L = 4096 flattened, NT vs row-major [E,D] weights)
    gemm_kernel<true , false, 0><<<gproj, blk>>>(q, Wq , nullptr, nullptr, qp, DD, DD, 0, 0, 0, nullptr, nullptr, 0.f);
    gemm_kernel<true , false, 0><<<gproj, blk>>>(k, Wk , nullptr, nullptr, kp, DD, DD, 0, 0, 0, nullptr, nullptr, 0.f);
    gemm_kernel<true , false, 0><<<gproj, blk>>>(v, Wv , nullptr, nullptr, vp, DD, DD, 0, 0, 0, nullptr, nullptr, 0.f);
    gemm_kernel<true , false, 0><<<gproj, blk>>>(q, Wqf, nullptr, nullptr, qf, DD, DD, 0, 0, 0, nullptr, nullptr, 0.f);
    gemm_kernel<true , false, 0><<<gproj, blk>>>(k, Wkf, nullptr, nullptr, kf, DD, DD, 0, 0, 0, nullptr, nullptr, 0.f);

    // 2) feature-similarity attention weights
    extract_kernel<<<(BB * LL * 16 + 255) / 256, 256>>>(x, xfc);
    feat_kernel<<<dim3(LL, BB), blk>>>(xfc, imp, lens, feat);

    // 3) qf2 / kf2 (batched NN)
    gemm_kernel<false, false, 0><<<gbat, blk>>>(feat, qf, nullptr, nullptr, qf2, LL, DD, BSTR, BSTR, BSTR, nullptr, nullptr, 0.f);
    gemm_kernel<false, false, 0><<<gbat, blk>>>(feat, kf, nullptr, nullptr, kf2, LL, DD, BSTR, BSTR, BSTR, nullptr, nullptr, 0.f);

    // 4) attn = tanh((qp.kp^T + qf2.kf2^T)/temp), key-masked (batched dual-NT)
    gemm_kernel<true , true , 1><<<gbat, blk>>>(qp, kp, qf2, kf2, attn_ptr, DD, LL, BSTR, BSTR, BSTR, nullptr, lens, scale);

    // 5) o1 = attn @ vp (batched NN)
    gemm_kernel<false, false, 0><<<gbat, blk>>>(attn_ptr, vp, nullptr, nullptr, o1, LL, DD, BSTR, BSTR, BSTR, nullptr, nullptr, 0.f);

    // 6) pre = o1 @ Wfc^T + q (NT + residual)
    gemm_kernel<true , false, 2><<<gproj, blk>>>(o1, Wfc, nullptr, nullptr, pre, DD, DD, 0, 0, 0, q, nullptr, 0.f);

    // 7) LayerNorm -> out
    ln_kernel<<<BB * LL, blk>>>(pre, gmm, bta, out);
}